// round 1
// baseline (speedup 1.0000x reference)
#include <cuda_runtime.h>
#include <math.h>

#define BB 8
#define CC 128
#define NN 512
#define TT 64
#define KTOP 409   // int(0.8*512)

// ---------------- scratch (device globals; no allocation) ----------------
__device__ float g_xw[(size_t)BB*CC*NN*TT];   // xw = W_w x + b     [B,C,N,T]
__device__ float g_xh[(size_t)BB*CC*NN*TT];   // diffusion output   [B,C,N,T]
__device__ float g_h [(size_t)BB*NN*CC];      // h[b,n,c]
__device__ float g_wh1[BB*NN];
__device__ float g_wh2[BB*NN];
__device__ float g_s [(size_t)2*BB*NN*NN];    // relu(scale*S1), relu(scale*S2)
__device__ float g_adj[(size_t)BB*NN*NN];     // masked adjacency  [b,n,m]
__device__ float g_M [CC*CC];                 // M = conv_w @ theta^T

// ---------------- K0: M[d][e] = sum_c conv_w[d,c]*theta[e,c] ----------------
__global__ void k0_kernel(const float* __restrict__ conv_w,
                          const float* __restrict__ theta)
{
    int d = blockIdx.x;        // 0..127
    int e = threadIdx.x;       // 0..127
    float s = 0.f;
    #pragma unroll 8
    for (int c = 0; c < CC; c++)
        s += __ldg(conv_w + d*CC + c) * __ldg(theta + e*CC + c);
    g_M[d*CC + e] = s;
}

// ---------------- K1: xw = W x + b ; h = sum_t xw ; Wh1/Wh2 ----------------
__global__ void __launch_bounds__(256) k1_kernel(
    const float* __restrict__ x, const float* __restrict__ Ww,
    const float* __restrict__ Wb, const float* __restrict__ av)
{
    extern __shared__ float sm[];
    float* Ws = sm;              // [128][130] padded
    float* Xs = sm + CC*130;     // [128][64]
    __shared__ float hpart[CC*8];
    __shared__ float rb1[8], rb2[8];

    const int tid = threadIdx.x;
    const int b = blockIdx.x >> 9;
    const int n = blockIdx.x & (NN-1);

    // load W (row-major, padded stride 130)
    for (int q = tid; q < CC*CC/4; q += 256) {
        int d  = q >> 5;
        int c0 = (q & 31) << 2;
        float4 w4 = *(const float4*)(Ww + d*CC + c0);
        float* dst = Ws + d*130 + c0;
        dst[0]=w4.x; dst[1]=w4.y; dst[2]=w4.z; dst[3]=w4.w;
    }
    // load X tile x[b,:,n,:]
    const float* xb = x + ((size_t)b*CC*NN + n) * TT;
    for (int q = tid; q < CC*TT/4; q += 256) {
        int c  = q >> 4;
        int t4 = (q & 15) << 2;
        *(float4*)(Xs + c*TT + t4) = *(const float4*)(xb + (size_t)c*NN*TT + t4);
    }
    __syncthreads();

    const int dg = tid >> 3, tg = tid & 7;
    const int d0 = dg*4, t0 = tg*8;
    float acc[4][8];
    #pragma unroll
    for (int i=0;i<4;i++)
        #pragma unroll
        for (int j=0;j<8;j++) acc[i][j]=0.f;

    #pragma unroll 2
    for (int c=0;c<CC;c++){
        float wv[4];
        #pragma unroll
        for (int i=0;i<4;i++) wv[i] = Ws[(d0+i)*130 + c];
        float4 xa = *(float4*)(Xs + c*TT + t0);
        float4 xc = *(float4*)(Xs + c*TT + t0 + 4);
        float xv[8] = {xa.x,xa.y,xa.z,xa.w,xc.x,xc.y,xc.z,xc.w};
        #pragma unroll
        for (int i=0;i<4;i++)
            #pragma unroll
            for (int j=0;j<8;j++) acc[i][j] += wv[i]*xv[j];
    }

    float* outp = g_xw + ((size_t)b*CC*NN + n) * TT;
    #pragma unroll
    for (int i=0;i<4;i++){
        float bias = Wb[d0+i];
        float rs = 0.f;
        #pragma unroll
        for (int j=0;j<8;j++){ acc[i][j] += bias; rs += acc[i][j]; }
        *(float4*)(outp + (size_t)(d0+i)*NN*TT + t0)
            = make_float4(acc[i][0],acc[i][1],acc[i][2],acc[i][3]);
        *(float4*)(outp + (size_t)(d0+i)*NN*TT + t0+4)
            = make_float4(acc[i][4],acc[i][5],acc[i][6],acc[i][7]);
        hpart[(d0+i)*8 + tg] = rs;
    }
    __syncthreads();

    float p1 = 0.f, p2 = 0.f;
    if (tid < CC){
        float hv = 0.f;
        #pragma unroll
        for (int j=0;j<8;j++) hv += hpart[tid*8+j];
        g_h[((size_t)b*NN+n)*CC + tid] = hv;
        p1 = hv*av[tid];
        p2 = hv*av[CC+tid];
    }
    #pragma unroll
    for (int o=16;o;o>>=1){
        p1 += __shfl_xor_sync(0xffffffffu,p1,o);
        p2 += __shfl_xor_sync(0xffffffffu,p2,o);
    }
    if ((tid&31)==0){ rb1[tid>>5]=p1; rb2[tid>>5]=p2; }
    __syncthreads();
    if (tid==0){
        float s1=0.f, s2=0.f;
        #pragma unroll
        for (int i=0;i<8;i++){ s1+=rb1[i]; s2+=rb2[i]; }
        g_wh1[b*NN+n]=s1; g_wh2[b*NN+n]=s2;
    }
}

// ---------------- K2a: S = relu(scale * A B^T)  (A=h[b], B=memory or h[b]) --
__global__ void __launch_bounds__(256) k2a_kernel(const float* __restrict__ mem)
{
    __shared__ float As[64][17];
    __shared__ float Bs[64][17];
    const int z = blockIdx.z, b = z>>1, which = z&1;
    const int n0 = blockIdx.x*64, m0 = blockIdx.y*64;
    const float* A  = g_h + (size_t)b*NN*CC;
    const float* Bp = which ? A : mem;
    float* out = g_s + (size_t)which*BB*NN*NN + (size_t)b*NN*NN;
    const int tid = threadIdx.x;
    const int nl0 = (tid>>4)*4, ml0 = (tid&15)*4;
    const int rr = tid>>2, kq = (tid&3)*4;

    float acc[4][4];
    #pragma unroll
    for (int i=0;i<4;i++)
        #pragma unroll
        for (int j=0;j<4;j++) acc[i][j]=0.f;

    for (int k0=0;k0<CC;k0+=16){
        float4 a4 = *(const float4*)(A  + (size_t)(n0+rr)*CC + k0 + kq);
        As[rr][kq  ]=a4.x; As[rr][kq+1]=a4.y; As[rr][kq+2]=a4.z; As[rr][kq+3]=a4.w;
        float4 b4 = *(const float4*)(Bp + (size_t)(m0+rr)*CC + k0 + kq);
        Bs[rr][kq  ]=b4.x; Bs[rr][kq+1]=b4.y; Bs[rr][kq+2]=b4.z; Bs[rr][kq+3]=b4.w;
        __syncthreads();
        #pragma unroll
        for (int k=0;k<16;k++){
            float ar[4], br[4];
            #pragma unroll
            for (int i=0;i<4;i++) ar[i]=As[nl0+i][k];
            #pragma unroll
            for (int j=0;j<4;j++) br[j]=Bs[ml0+j][k];
            #pragma unroll
            for (int i=0;i<4;i++)
                #pragma unroll
                for (int j=0;j<4;j++) acc[i][j] += ar[i]*br[j];
        }
        __syncthreads();
    }
    const float scale = 0.08838834764831845f;  // 1/sqrt(128)
    #pragma unroll
    for (int i=0;i<4;i++){
        float4 v;
        v.x = fmaxf(acc[i][0]*scale, 0.f);
        v.y = fmaxf(acc[i][1]*scale, 0.f);
        v.z = fmaxf(acc[i][2]*scale, 0.f);
        v.w = fmaxf(acc[i][3]*scale, 0.f);
        *(float4*)(out + (size_t)(n0+nl0+i)*NN + m0 + ml0) = v;
    }
}

// ---------------- K2b: softmaxes + combine + softmax + top-k mask ----------
__device__ __forceinline__ float blkMax(float v, float* buf){
    #pragma unroll
    for (int o=16;o;o>>=1) v = fmaxf(v, __shfl_xor_sync(0xffffffffu,v,o));
    if ((threadIdx.x&31)==0) buf[threadIdx.x>>5]=v;
    __syncthreads();
    float r = buf[0];
    #pragma unroll
    for (int i=1;i<8;i++) r = fmaxf(r, buf[i]);
    __syncthreads();
    return r;
}
__device__ __forceinline__ float blkSum(float v, float* buf){
    #pragma unroll
    for (int o=16;o;o>>=1) v += __shfl_xor_sync(0xffffffffu,v,o);
    if ((threadIdx.x&31)==0) buf[threadIdx.x>>5]=v;
    __syncthreads();
    float r = 0.f;
    #pragma unroll
    for (int i=0;i<8;i++) r += buf[i];
    __syncthreads();
    return r;
}

__global__ void __launch_bounds__(256) k2b_kernel(
    const float* __restrict__ cw,  const float* __restrict__ cwa,
    const float* __restrict__ fcw, const float* __restrict__ fcb)
{
    __shared__ float awrow[NN];
    __shared__ float sb[NN];
    __shared__ float rbuf[8];
    __shared__ int   ibuf[8];
    const int tid = threadIdx.x;
    const int b = blockIdx.x >> 9, n = blockIdx.x & (NN-1);
    const size_t rowoff = ((size_t)b*NN + n)*NN;
    const float* s1r = g_s + rowoff;
    const float* s2r = g_s + (size_t)BB*NN*NN + rowoff;

    float v1[2], v2[2];
    v1[0]=s1r[tid]; v1[1]=s1r[tid+256];
    v2[0]=s2r[tid]; v2[1]=s2r[tid+256];

    float m1 = blkMax(fmaxf(v1[0],v1[1]), rbuf);
    float e1a=expf(v1[0]-m1), e1b=expf(v1[1]-m1);
    float z1 = blkSum(e1a+e1b, rbuf);
    float a1[2] = {e1a/z1, e1b/z1};

    float m2 = blkMax(fmaxf(v2[0],v2[1]), rbuf);
    float e2a=expf(v2[0]-m2), e2b=expf(v2[1]-m2);
    float z2 = blkSum(e2a+e2b, rbuf);
    float a2[2] = {e2a/z2, e2b/z2};

    float wh1n = g_wh1[b*NN+n];
    float f0 = fcw[0], f1 = fcw[1], fb = fcb[0];
    float l[2];
    #pragma unroll
    for (int r=0;r<2;r++){
        int m_ = tid + r*256;
        float af = f0*a1[r] + f1*a2[r] + fb;
        l[r] = (wh1n + g_wh2[b*NN+m_]) * cw[(size_t)n*NN+m_]
             + af * cwa[(size_t)n*NN+m_];
    }
    float lm = blkMax(fmaxf(l[0],l[1]), rbuf);
    float ea = expf(l[0]-lm), eb = expf(l[1]-lm);
    float z  = blkSum(ea+eb, rbuf);
    float aw[2] = {ea/z, eb/z};

    awrow[tid]=aw[0]; awrow[tid+256]=aw[1];
    sb[tid]=aw[0];    sb[tid+256]=aw[1];
    __syncthreads();

    // bitonic sort ascending, 512 elems / 256 threads
    for (int ks=2; ks<=NN; ks<<=1){
        for (int j=ks>>1; j>0; j>>=1){
            #pragma unroll
            for (int rep=0; rep<2; rep++){
                int idx = tid + rep*256;
                int ixj = idx ^ j;
                if (ixj > idx){
                    float x0 = sb[idx], x1 = sb[ixj];
                    bool up = ((idx & ks) == 0);
                    bool sw = up ? (x0 > x1) : (x0 < x1);
                    if (sw){ sb[idx]=x1; sb[ixj]=x0; }
                }
            }
            __syncthreads();
        }
    }
    float thr = sb[NN - KTOP];   // 409th largest

    int cgt = (aw[0] > thr) + (aw[1] > thr);
    #pragma unroll
    for (int o=16;o;o>>=1) cgt += __shfl_xor_sync(0xffffffffu,cgt,o);
    if ((tid&31)==0) ibuf[tid>>5]=cgt;
    __syncthreads();
    if (tid==0){
        int tot=0;
        #pragma unroll
        for (int i=0;i<8;i++) tot += ibuf[i];
        int need = KTOP - tot;  // how many == thr to keep (lowest index first)
        for (int m_=0; m_<NN; m_++){
            float v = awrow[m_];
            if (v == thr){ if (need>0) need--; else awrow[m_] = 0.f; }
        }
    }
    __syncthreads();

    float* outr = g_adj + rowoff;
    #pragma unroll
    for (int r=0;r<2;r++){
        int m_ = tid + r*256;
        float v = awrow[m_];
        outr[m_] = (v >= thr) ? v : 0.f;
    }
}

// ---------------- K3: xh[b,c,m,t] = sum_n adj[b,n,m] * xw[b,c,n,t] ---------
__global__ void __launch_bounds__(256) k3_kernel()
{
    __shared__ float As[16][64];
    __shared__ float Bs[16][64];
    const int mt = blockIdx.x, c = blockIdx.y, b = blockIdx.z;
    const int m0 = mt*64;
    const int tid = threadIdx.x;
    const int ml0 = (tid & 15)*4, tl0 = (tid >> 4)*4;
    const int lk = tid >> 4, lq = (tid & 15)*4;

    float acc[4][4];
    #pragma unroll
    for (int i=0;i<4;i++)
        #pragma unroll
        for (int j=0;j<4;j++) acc[i][j]=0.f;

    const float* adjb = g_adj + (size_t)b*NN*NN;
    const float* xwb  = g_xw + ((size_t)b*CC + c)*NN*TT;

    for (int n0=0; n0<NN; n0+=16){
        *(float4*)&As[lk][lq] = *(const float4*)(adjb + (size_t)(n0+lk)*NN + m0 + lq);
        *(float4*)&Bs[lk][lq] = *(const float4*)(xwb  + (size_t)(n0+lk)*TT + lq);
        __syncthreads();
        #pragma unroll
        for (int k=0;k<16;k++){
            float4 a4 = *(float4*)&As[k][ml0];
            float4 b4 = *(float4*)&Bs[k][tl0];
            float ar[4] = {a4.x,a4.y,a4.z,a4.w};
            float br[4] = {b4.x,b4.y,b4.z,b4.w};
            #pragma unroll
            for (int i=0;i<4;i++)
                #pragma unroll
                for (int j=0;j<4;j++) acc[i][j] += ar[i]*br[j];
        }
        __syncthreads();
    }
    float* outp = g_xh + ((size_t)b*CC + c)*NN*TT;
    #pragma unroll
    for (int i=0;i<4;i++)
        *(float4*)(outp + (size_t)(m0+ml0+i)*TT + tl0)
            = make_float4(acc[i][0],acc[i][1],acc[i][2],acc[i][3]);
}

// ---------------- K4: out = (M xh + conv_b) * emb + x ----------------------
__global__ void __launch_bounds__(256) k4_kernel(
    const float* __restrict__ x, const float* __restrict__ cb,
    const float* __restrict__ emb, float* __restrict__ outg)
{
    extern __shared__ float sm[];
    float* Ms = sm;              // [128][130]
    float* Xs = sm + CC*130;     // [128][64]
    const int tid = threadIdx.x;
    const int b = blockIdx.x >> 9;
    const int n = blockIdx.x & (NN-1);

    for (int q = tid; q < CC*CC/4; q += 256) {
        int d  = q >> 5;
        int c0 = (q & 31) << 2;
        float4 w4 = *(const float4*)(g_M + d*CC + c0);
        float* dst = Ms + d*130 + c0;
        dst[0]=w4.x; dst[1]=w4.y; dst[2]=w4.z; dst[3]=w4.w;
    }
    const float* xhb = g_xh + ((size_t)b*CC*NN + n) * TT;
    for (int q = tid; q < CC*TT/4; q += 256) {
        int c  = q >> 4;
        int t4 = (q & 15) << 2;
        *(float4*)(Xs + c*TT + t4) = *(const float4*)(xhb + (size_t)c*NN*TT + t4);
    }
    __syncthreads();

    const int dg = tid >> 3, tg = tid & 7;
    const int d0 = dg*4, t0 = tg*8;
    float acc[4][8];
    #pragma unroll
    for (int i=0;i<4;i++)
        #pragma unroll
        for (int j=0;j<8;j++) acc[i][j]=0.f;

    #pragma unroll 2
    for (int c=0;c<CC;c++){
        float wv[4];
        #pragma unroll
        for (int i=0;i<4;i++) wv[i] = Ms[(d0+i)*130 + c];
        float4 xa = *(float4*)(Xs + c*TT + t0);
        float4 xc = *(float4*)(Xs + c*TT + t0 + 4);
        float xv[8] = {xa.x,xa.y,xa.z,xa.w,xc.x,xc.y,xc.z,xc.w};
        #pragma unroll
        for (int i=0;i<4;i++)
            #pragma unroll
            for (int j=0;j<8;j++) acc[i][j] += wv[i]*xv[j];
    }

    const float* xb = x    + ((size_t)b*CC*NN + n) * TT;
    float*       op = outg + ((size_t)b*CC*NN + n) * TT;
    #pragma unroll
    for (int i=0;i<4;i++){
        int d = d0 + i;
        float bias = cb[d];
        float ev = emb[d*NN + n];
        float4 s0 = *(const float4*)(xb + (size_t)d*NN*TT + t0);
        float4 s1 = *(const float4*)(xb + (size_t)d*NN*TT + t0 + 4);
        float sk[8] = {s0.x,s0.y,s0.z,s0.w,s1.x,s1.y,s1.z,s1.w};
        float r[8];
        #pragma unroll
        for (int j=0;j<8;j++) r[j] = (acc[i][j] + bias)*ev + sk[j];
        *(float4*)(op + (size_t)d*NN*TT + t0)     = make_float4(r[0],r[1],r[2],r[3]);
        *(float4*)(op + (size_t)d*NN*TT + t0 + 4) = make_float4(r[4],r[5],r[6],r[7]);
    }
}

// ---------------- launch -----------------------------------------------------
extern "C" void kernel_launch(void* const* d_in, const int* in_sizes, int n_in,
                              void* d_out, int out_size)
{
    const float* x      = (const float*)d_in[0];
    const float* Ww     = (const float*)d_in[1];
    const float* Wb     = (const float*)d_in[2];
    const float* conv_w = (const float*)d_in[3];
    const float* conv_b = (const float*)d_in[4];
    const float* theta  = (const float*)d_in[5];
    const float* memory = (const float*)d_in[6];
    const float* a_vec  = (const float*)d_in[7];
    const float* cw     = (const float*)d_in[8];
    const float* cwa    = (const float*)d_in[9];
    const float* fcw    = (const float*)d_in[10];
    const float* fcb    = (const float*)d_in[11];
    const float* emb    = (const float*)d_in[12];
    float* out = (float*)d_out;

    const int smem1 = (CC*130 + CC*TT) * 4;   // 99328 bytes
    cudaFuncSetAttribute(k1_kernel, cudaFuncAttributeMaxDynamicSharedMemorySize, smem1);
    cudaFuncSetAttribute(k4_kernel, cudaFuncAttributeMaxDynamicSharedMemorySize, smem1);

    k0_kernel<<<CC, CC>>>(conv_w, theta);
    k1_kernel<<<BB*NN, 256, smem1>>>(x, Ww, Wb, a_vec);
    k2a_kernel<<<dim3(8,8,16), 256>>>(memory);
    k2b_kernel<<<BB*NN, 256>>>(cw, cwa, fcw, fcb);
    k3_kernel<<<dim3(8,CC,BB), 256>>>();
    k4_kernel<<<BB*NN, 256, smem1>>>(x, conv_b, emb, out);
}